// round 4
// baseline (speedup 1.0000x reference)
#include <cuda_runtime.h>

// out = x^2 * 0.1 over 64M fp32. HBM-bound streaming kernel.
// v4: persistent grid (one resident wave, 592 CTAs), each CTA loops over
//     8x-float4 batched chunks. No wave transitions -> chip-wide MLP stays
//     flat for the whole kernel. Streaming cache hints (zero reuse).

#define THREADS 256
#define UNROLL  8
#define PERSIST_BLOCKS 592   // 148 SMs x 4 CTAs (48 regs, 256 thr -> fits)

__global__ void __launch_bounds__(THREADS) poly_kernel_persist(
    const float4* __restrict__ x, float4* __restrict__ out, int n4)
{
    const int chunk = THREADS * UNROLL;                  // float4s per CTA-iteration
    const int tid = threadIdx.x;
    const int nchunks = n4 / chunk;                      // exact cover assumed by caller

    for (int c = blockIdx.x; c < nchunks; c += gridDim.x) {
        const int base = c * chunk + tid;

        float4 v[UNROLL];
#pragma unroll
        for (int u = 0; u < UNROLL; u++)
            v[u] = __ldcs(&x[base + u * THREADS]);

#pragma unroll
        for (int u = 0; u < UNROLL; u++) {
            float4 r;
            r.x = v[u].x * v[u].x * 0.1f;
            r.y = v[u].y * v[u].y * 0.1f;
            r.z = v[u].z * v[u].z * 0.1f;
            r.w = v[u].w * v[u].w * 0.1f;
            __stcs(&out[base + u * THREADS], r);
        }
    }
}

// Generic fallback (any n).
__global__ void __launch_bounds__(THREADS) poly_kernel_generic(
    const float* __restrict__ x, float* __restrict__ out, int n)
{
    const int stride = gridDim.x * THREADS;
    for (int i = blockIdx.x * THREADS + threadIdx.x; i < n; i += stride) {
        float v = x[i];
        out[i] = v * v * 0.1f;
    }
}

extern "C" void kernel_launch(void* const* d_in, const int* in_sizes, int n_in,
                              void* d_out, int out_size) {
    const float* x = (const float*)d_in[0];
    float* out = (float*)d_out;
    int n = in_sizes[0];

    const int chunk_elems = THREADS * UNROLL * 4;        // floats per CTA-iteration
    if ((n % chunk_elems) == 0) {
        int n4 = n / 4;
        int nchunks = n4 / (THREADS * UNROLL);
        int blocks = PERSIST_BLOCKS < nchunks ? PERSIST_BLOCKS : nchunks;
        poly_kernel_persist<<<blocks, THREADS>>>((const float4*)x, (float4*)out, n4);
    } else {
        int blocks = (n + THREADS - 1) / THREADS;
        if (blocks > 65536) blocks = 65536;
        poly_kernel_generic<<<blocks, THREADS>>>(x, out, n);
    }
}

// round 5
// speedup vs baseline: 1.1009x; 1.1009x over previous
#include <cuda_runtime.h>

// out = x^2 * 0.1 over 64M fp32. HBM-bound streaming kernel.
// v5: back to exact-cover one-shot grid (R3 structure, best kernel time),
//     MLP=8 front-batched float4 per thread, but with __launch_bounds__(256, 6)
//     to lift occupancy 50% -> ~75% at the same per-thread MLP.

#define THREADS 256
#define UNROLL  8

// Fast path: grid exactly covers n4 = gridDim.x * THREADS * UNROLL.
__global__ void __launch_bounds__(THREADS, 6) poly_kernel_exact(
    const float4* __restrict__ x, float4* __restrict__ out)
{
    const int stride = gridDim.x * THREADS;
    const int base = blockIdx.x * THREADS + threadIdx.x;

    float4 v[UNROLL];
#pragma unroll
    for (int u = 0; u < UNROLL; u++)
        v[u] = __ldcs(&x[base + u * stride]);

#pragma unroll
    for (int u = 0; u < UNROLL; u++) {
        float4 r;
        r.x = v[u].x * v[u].x * 0.1f;
        r.y = v[u].y * v[u].y * 0.1f;
        r.z = v[u].z * v[u].z * 0.1f;
        r.w = v[u].w * v[u].w * 0.1f;
        __stcs(&out[base + u * stride], r);
    }
}

// Generic fallback (any n).
__global__ void __launch_bounds__(THREADS) poly_kernel_generic(
    const float* __restrict__ x, float* __restrict__ out, int n)
{
    const int stride = gridDim.x * THREADS;
    for (int i = blockIdx.x * THREADS + threadIdx.x; i < n; i += stride) {
        float v = x[i];
        out[i] = v * v * 0.1f;
    }
}

extern "C" void kernel_launch(void* const* d_in, const int* in_sizes, int n_in,
                              void* d_out, int out_size) {
    const float* x = (const float*)d_in[0];
    float* out = (float*)d_out;
    int n = in_sizes[0];

    const int per_block = THREADS * UNROLL;          // float4s per block
    if ((n % 4) == 0 && ((n / 4) % per_block) == 0) {
        int n4 = n / 4;
        int blocks = n4 / per_block;                 // 16M / 2048 = 8192
        poly_kernel_exact<<<blocks, THREADS>>>((const float4*)x, (float4*)out);
    } else {
        int blocks = (n + THREADS - 1) / THREADS;
        if (blocks > 65536) blocks = 65536;
        poly_kernel_generic<<<blocks, THREADS>>>(x, out, n);
    }
}

// round 6
// speedup vs baseline: 1.1202x; 1.0175x over previous
#include <cuda_runtime.h>

// out = x^2 * 0.1 over 64M fp32. HBM-bound streaming kernel.
// v6: exact-cover grid, MLP=8 front-batched float4 per thread, natural regalloc
//     (no launch_bounds cap — R5 showed caps induce spill traffic), but
//     THREADS=128 so the 48-reg footprint packs 10 CTAs/SM (62.5% occ) instead
//     of 5 CTAs at 256 threads (50% occ). 2^24 float4 / (128*8) = 16384 blocks.

#define THREADS 128
#define UNROLL  8

__global__ void __launch_bounds__(THREADS) poly_kernel_exact(
    const float4* __restrict__ x, float4* __restrict__ out)
{
    const int stride = gridDim.x * THREADS;
    const int base = blockIdx.x * THREADS + threadIdx.x;

    float4 v[UNROLL];
#pragma unroll
    for (int u = 0; u < UNROLL; u++)
        v[u] = __ldcs(&x[base + u * stride]);

#pragma unroll
    for (int u = 0; u < UNROLL; u++) {
        float4 r;
        r.x = v[u].x * v[u].x * 0.1f;
        r.y = v[u].y * v[u].y * 0.1f;
        r.z = v[u].z * v[u].z * 0.1f;
        r.w = v[u].w * v[u].w * 0.1f;
        __stcs(&out[base + u * stride], r);
    }
}

// Generic fallback (any n).
__global__ void __launch_bounds__(256) poly_kernel_generic(
    const float* __restrict__ x, float* __restrict__ out, int n)
{
    const int stride = gridDim.x * 256;
    for (int i = blockIdx.x * 256 + threadIdx.x; i < n; i += stride) {
        float v = x[i];
        out[i] = v * v * 0.1f;
    }
}

extern "C" void kernel_launch(void* const* d_in, const int* in_sizes, int n_in,
                              void* d_out, int out_size) {
    const float* x = (const float*)d_in[0];
    float* out = (float*)d_out;
    int n = in_sizes[0];

    const int per_block = THREADS * UNROLL;          // float4s per block = 1024
    if ((n % 4) == 0 && ((n / 4) % per_block) == 0) {
        int n4 = n / 4;
        int blocks = n4 / per_block;                 // 16M / 1024 = 16384
        poly_kernel_exact<<<blocks, THREADS>>>((const float4*)x, (float4*)out);
    } else {
        int blocks = (n + 255) / 256;
        if (blocks > 65536) blocks = 65536;
        poly_kernel_generic<<<blocks, 256>>>(x, out, n);
    }
}

// round 7
// speedup vs baseline: 1.1206x; 1.0004x over previous
#include <cuda_runtime.h>
#include <cstdint>

// out = x^2 * 0.1 over 64M fp32. HBM-bound streaming kernel.
// v7: 256-bit global accesses (ld/st.global.v8.f32, sm_100a+). 32B per
//     instruction halves LDG/STG count and L1tex wavefront pressure per byte.
//     4 x v8 per thread (128B/thread), exact-cover grid, streaming (.cs) ops.

#define THREADS 256
#define UNROLL  4   // 4 x 8 floats = 32 floats = 128 bytes per thread

__device__ __forceinline__ void ldg_v8_cs(const float* p, float* r) {
    asm volatile(
        "ld.global.cs.v8.f32 {%0, %1, %2, %3, %4, %5, %6, %7}, [%8];"
        : "=f"(r[0]), "=f"(r[1]), "=f"(r[2]), "=f"(r[3]),
          "=f"(r[4]), "=f"(r[5]), "=f"(r[6]), "=f"(r[7])
        : "l"(p));
}

__device__ __forceinline__ void stg_v8_cs(float* p, const float* r) {
    asm volatile(
        "st.global.cs.v8.f32 [%0], {%1, %2, %3, %4, %5, %6, %7, %8};"
        :: "l"(p),
           "f"(r[0]), "f"(r[1]), "f"(r[2]), "f"(r[3]),
           "f"(r[4]), "f"(r[5]), "f"(r[6]), "f"(r[7])
        : "memory");
}

// Exact cover: n floats == gridDim.x * THREADS * UNROLL * 8.
__global__ void __launch_bounds__(THREADS) poly_kernel_v8(
    const float* __restrict__ x, float* __restrict__ out)
{
    const long long stride8 = (long long)gridDim.x * THREADS;   // in 8-float units
    const long long base8 = (long long)blockIdx.x * THREADS + threadIdx.x;

    float v[UNROLL][8];
#pragma unroll
    for (int u = 0; u < UNROLL; u++)
        ldg_v8_cs(x + (base8 + u * stride8) * 8, v[u]);

#pragma unroll
    for (int u = 0; u < UNROLL; u++) {
        float r[8];
#pragma unroll
        for (int e = 0; e < 8; e++)
            r[e] = v[u][e] * v[u][e] * 0.1f;
        stg_v8_cs(out + (base8 + u * stride8) * 8, r);
    }
}

// Generic fallback (any n).
__global__ void __launch_bounds__(256) poly_kernel_generic(
    const float* __restrict__ x, float* __restrict__ out, int n)
{
    const int stride = gridDim.x * 256;
    for (int i = blockIdx.x * 256 + threadIdx.x; i < n; i += stride) {
        float v = x[i];
        out[i] = v * v * 0.1f;
    }
}

extern "C" void kernel_launch(void* const* d_in, const int* in_sizes, int n_in,
                              void* d_out, int out_size) {
    const float* x = (const float*)d_in[0];
    float* out = (float*)d_out;
    int n = in_sizes[0];

    const int per_block = THREADS * UNROLL * 8;      // floats per block = 8192
    if ((n % per_block) == 0) {
        int blocks = n / per_block;                  // 64M / 8192 = 8192
        poly_kernel_v8<<<blocks, THREADS>>>(x, out);
    } else {
        int blocks = (n + 255) / 256;
        if (blocks > 65536) blocks = 65536;
        poly_kernel_generic<<<blocks, 256>>>(x, out, n);
    }
}

// round 8
// speedup vs baseline: 1.1246x; 1.0035x over previous
#include <cuda_runtime.h>

// out = x^2 * 0.1 over 64M fp32. HBM-bound streaming kernel.
// v8: exact-cover one-shot grid (best family), MLP=8 float4 per thread, but
//     block-LOCAL contiguous layout: each CTA owns one contiguous 32KB chunk
//     (2048 float4), thread offsets u*256 within it -> denser per-channel
//     page locality vs the 32MB-apart strided batching of earlier rounds.

#define THREADS 256
#define UNROLL  8

__global__ void __launch_bounds__(THREADS) poly_kernel_local(
    const float4* __restrict__ x, float4* __restrict__ out)
{
    const int base = blockIdx.x * (THREADS * UNROLL) + threadIdx.x;

    float4 v[UNROLL];
#pragma unroll
    for (int u = 0; u < UNROLL; u++)
        v[u] = __ldcs(&x[base + u * THREADS]);

#pragma unroll
    for (int u = 0; u < UNROLL; u++) {
        float4 r;
        r.x = v[u].x * v[u].x * 0.1f;
        r.y = v[u].y * v[u].y * 0.1f;
        r.z = v[u].z * v[u].z * 0.1f;
        r.w = v[u].w * v[u].w * 0.1f;
        __stcs(&out[base + u * THREADS], r);
    }
}

// Generic fallback (any n).
__global__ void __launch_bounds__(256) poly_kernel_generic(
    const float* __restrict__ x, float* __restrict__ out, int n)
{
    const int stride = gridDim.x * 256;
    for (int i = blockIdx.x * 256 + threadIdx.x; i < n; i += stride) {
        float v = x[i];
        out[i] = v * v * 0.1f;
    }
}

extern "C" void kernel_launch(void* const* d_in, const int* in_sizes, int n_in,
                              void* d_out, int out_size) {
    const float* x = (const float*)d_in[0];
    float* out = (float*)d_out;
    int n = in_sizes[0];

    const int per_block = THREADS * UNROLL;          // float4s per block = 2048
    if ((n % 4) == 0 && ((n / 4) % per_block) == 0) {
        int n4 = n / 4;
        int blocks = n4 / per_block;                 // 16M / 2048 = 8192
        poly_kernel_local<<<blocks, THREADS>>>((const float4*)x, (float4*)out);
    } else {
        int blocks = (n + 255) / 256;
        if (blocks > 65536) blocks = 65536;
        poly_kernel_generic<<<blocks, 256>>>(x, out, n);
    }
}